// round 4
// baseline (speedup 1.0000x reference)
#include <cuda_runtime.h>
#include <cstdint>

// Problem constants
#define BDIM 128
#define TDIM 2048
#define HDIM 200
#define HP   208      // H padded to 26*8 for mma N-tiling
#define TILE_T 64
#define NKSTEP 25     // 200 / 8

// Scratch (allocation-free rule: __device__ globals)
__device__ float g_qp[BDIM * HP];     // qp[b,h] = h0@Wa^T + ba + bua (padded w/ 0)
__device__ float g_ctx[BDIM * HDIM];  // attention context per batch

__device__ __forceinline__ float cvt_tf32(float x) {
    uint32_t u;
    asm("cvt.rna.tf32.f32 %0, %1;" : "=r"(u) : "f"(x));
    return __uint_as_float(u);
}

__device__ __forceinline__ void mma_tf32(float* d,
    uint32_t a0, uint32_t a1, uint32_t a2, uint32_t a3,
    uint32_t b0, uint32_t b1) {
    asm volatile(
        "mma.sync.aligned.m16n8k8.row.col.f32.tf32.tf32.f32 "
        "{%0,%1,%2,%3}, {%4,%5,%6,%7}, {%8,%9}, {%0,%1,%2,%3};"
        : "+f"(d[0]), "+f"(d[1]), "+f"(d[2]), "+f"(d[3])
        : "r"(a0), "r"(a1), "r"(a2), "r"(a3), "r"(b0), "r"(b1));
}

// ---------------------------------------------------------------------------
// Kernel 0: qp[b,:] = h0[0,b,:] @ Wa^T + ba + bua   (padded to HP with zeros)
// ---------------------------------------------------------------------------
__global__ void qp_kernel(const float* __restrict__ h0,
                          const float* __restrict__ Wa,
                          const float* __restrict__ ba,
                          const float* __restrict__ bua) {
    __shared__ float q_s[HDIM];
    int b = blockIdx.x, tid = threadIdx.x;
    for (int i = tid; i < HDIM; i += blockDim.x) q_s[i] = h0[b * HDIM + i];
    __syncthreads();
    for (int i = tid; i < HP; i += blockDim.x) {
        float acc = 0.f;
        if (i < HDIM) {
            acc = ba[i] + bua[i];
            const float* w = Wa + i * HDIM;
            #pragma unroll 4
            for (int k = 0; k < HDIM; k++) acc += q_s[k] * w[k];
        }
        g_qp[b * HP + i] = acc;
    }
}

// ---------------------------------------------------------------------------
// Kernel 1: fused scores (tf32 mma) + tanh/Va epilogue + online softmax +
//           context accumulation. One CTA per batch, Ua resident in smem.
// smem: Ua_s[HP*HDIM] | E_s[TILE_T*HDIM] | qp_s[HP] | va_s[HP] |
//       s_s[2*TILE_T] | w_s[TILE_T] | ctx_s[HDIM] | scal[8]
// ---------------------------------------------------------------------------
__global__ void __launch_bounds__(256, 1)
attn_kernel(const float* __restrict__ enc,
            const float* __restrict__ Ua,
            const float* __restrict__ Va) {
    extern __shared__ float sm[];
    float* Ua_s  = sm;                       // HP*HDIM  (tf32-rounded, rows>=200 zero)
    float* E_s   = Ua_s + HP * HDIM;         // TILE_T*HDIM (tf32-rounded)
    float* qp_s  = E_s + TILE_T * HDIM;      // HP
    float* va_s  = qp_s + HP;                // HP (zero-padded)
    float* s_s   = va_s + HP;                // 2*TILE_T: per-(n-half) partial scores
    float* w_s   = s_s + 2 * TILE_T;         // TILE_T
    float* ctx_s = w_s + TILE_T;             // HDIM
    float* scal  = ctx_s + HDIM;             // [0]=running m, [1]=running l, [2]=scale, [3]=newm

    const int b = blockIdx.x, tid = threadIdx.x;

    // Load Ua (tf32-rounded), zero padded rows
    const float4* Ua4 = (const float4*)Ua;
    for (int i = tid; i < HDIM * HDIM / 4; i += 256) {
        float4 v = Ua4[i];
        v.x = cvt_tf32(v.x); v.y = cvt_tf32(v.y);
        v.z = cvt_tf32(v.z); v.w = cvt_tf32(v.w);
        ((float4*)Ua_s)[i] = v;
    }
    for (int i = HDIM * HDIM + tid; i < HP * HDIM; i += 256) Ua_s[i] = 0.f;
    for (int i = tid; i < HP; i += 256) {
        qp_s[i] = g_qp[b * HP + i];
        va_s[i] = (i < HDIM) ? Va[i] : 0.f;
    }
    for (int i = tid; i < HDIM; i += 256) ctx_s[i] = 0.f;
    if (tid == 0) { scal[0] = -1e30f; scal[1] = 0.f; }
    __syncthreads();

    const int lane = tid & 31;
    const int wid  = tid >> 5;
    const int g    = lane >> 2;   // groupID
    const int c    = lane & 3;    // threadID_in_group
    const int wm   = wid & 3;     // t sub-tile (16 rows each)
    const int wn   = wid >> 2;    // h half (104 each)
    const int arow0 = 16 * wm + g;

    for (int tile = 0; tile < TDIM / TILE_T; ++tile) {
        // ---- load E tile (contiguous 64x200 block), tf32-round once ----
        const float4* ep4 =
            (const float4*)(enc + ((size_t)b * TDIM + (size_t)tile * TILE_T) * HDIM);
        for (int i = tid; i < TILE_T * HDIM / 4; i += 256) {
            float4 v = ep4[i];
            v.x = cvt_tf32(v.x); v.y = cvt_tf32(v.y);
            v.z = cvt_tf32(v.z); v.w = cvt_tf32(v.w);
            ((float4*)E_s)[i] = v;
        }
        __syncthreads();

        // ---- GEMM: C[t,h] = sum_k E[t,k] * Ua[h,k] ----
        float acc[13][4];
        #pragma unroll
        for (int j = 0; j < 13; j++) {
            acc[j][0] = 0.f; acc[j][1] = 0.f; acc[j][2] = 0.f; acc[j][3] = 0.f;
        }
        const float* Ea = E_s + arow0 * HDIM;
        const float* Eb = Ea + 8 * HDIM;
        #pragma unroll 5
        for (int ks = 0; ks < NKSTEP; ks++) {
            const int kb = ks * 8;
            uint32_t a0 = __float_as_uint(Ea[kb + c]);
            uint32_t a1 = __float_as_uint(Eb[kb + c]);
            uint32_t a2 = __float_as_uint(Ea[kb + c + 4]);
            uint32_t a3 = __float_as_uint(Eb[kb + c + 4]);
            #pragma unroll
            for (int j = 0; j < 13; j++) {
                const int hrow = 104 * wn + 8 * j + g;
                uint32_t b0 = __float_as_uint(Ua_s[hrow * HDIM + kb + c]);
                uint32_t b1 = __float_as_uint(Ua_s[hrow * HDIM + kb + c + 4]);
                mma_tf32(acc[j], a0, a1, a2, a3, b0, b1);
            }
        }

        // ---- epilogue: s[t] partial = sum_h Va[h]*tanh(qp[h]+C[t,h]) ----
        float p0 = 0.f, p8 = 0.f;
        #pragma unroll
        for (int j = 0; j < 13; j++) {
            const int hb = 104 * wn + 8 * j + 2 * c;
            p0 += va_s[hb]     * tanhf(qp_s[hb]     + acc[j][0]);
            p0 += va_s[hb + 1] * tanhf(qp_s[hb + 1] + acc[j][1]);
            p8 += va_s[hb]     * tanhf(qp_s[hb]     + acc[j][2]);
            p8 += va_s[hb + 1] * tanhf(qp_s[hb + 1] + acc[j][3]);
        }
        p0 += __shfl_xor_sync(0xffffffffu, p0, 1);
        p0 += __shfl_xor_sync(0xffffffffu, p0, 2);
        p8 += __shfl_xor_sync(0xffffffffu, p8, 1);
        p8 += __shfl_xor_sync(0xffffffffu, p8, 2);
        if (c == 0) {   // deterministic: each (wn, row) slot written by exactly one lane
            s_s[wn * TILE_T + 16 * wm + g]     = p0;
            s_s[wn * TILE_T + 16 * wm + g + 8] = p8;
        }
        __syncthreads();
        if (tid < TILE_T) s_s[tid] = s_s[tid] + s_s[TILE_T + tid];
        __syncthreads();

        // ---- online softmax update ----
        if (tid < 32) {
            float v = fmaxf(s_s[tid], s_s[tid + 32]);
            #pragma unroll
            for (int off = 16; off > 0; off >>= 1)
                v = fmaxf(v, __shfl_xor_sync(0xffffffffu, v, off));
            if (tid == 0) {
                float mo = scal[0];
                float nm = fmaxf(mo, v);
                scal[2] = __expf(mo - nm);   // 0 on first tile (mo = -1e30)
                scal[3] = nm;
                scal[0] = nm;
            }
        }
        __syncthreads();
        const float nm = scal[3], scale = scal[2];
        if (tid < TILE_T) w_s[tid] = __expf(s_s[tid] - nm);
        __syncthreads();
        if (tid < 32) {
            float sv = w_s[tid] + w_s[tid + 32];
            #pragma unroll
            for (int off = 16; off > 0; off >>= 1)
                sv += __shfl_xor_sync(0xffffffffu, sv, off);
            if (tid == 0) scal[1] = scal[1] * scale + sv;
        }
        // ---- context accumulation from the E tile already in smem ----
        if (tid < HDIM) {
            float a = ctx_s[tid] * scale;
            const float* ec = E_s + tid;
            #pragma unroll 8
            for (int t = 0; t < TILE_T; t++) a += w_s[t] * ec[t * HDIM];
            ctx_s[tid] = a;
        }
        __syncthreads();
    }
    if (tid < HDIM) g_ctx[b * HDIM + tid] = ctx_s[tid] / scal[1];
}

// ---------------------------------------------------------------------------
// Kernel 2: decoder. c_prev=c0 and h_pre are constant; IN=1 so only the
// scalar x_t changes each step -> gates_t = G_const + x_t * W_ih[:,0].
// One CTA per batch runs the whole 5-step recurrence in smem.
// ---------------------------------------------------------------------------
__global__ void __launch_bounds__(256, 1)
dec_kernel(const float* __restrict__ x_in, const float* __restrict__ h0,
           const float* __restrict__ c0,
           const float* __restrict__ W_ih, const float* __restrict__ W_hh,
           const float* __restrict__ b_ih, const float* __restrict__ b_hh,
           const float* __restrict__ W1, const float* __restrict__ b1,
           const float* __restrict__ W2, const float* __restrict__ b2,
           const float* __restrict__ W3, const float* __restrict__ b3,
           float* __restrict__ out) {
    extern __shared__ float sm[];
    float* ctx_s = sm;                  // 200
    float* q_s   = ctx_s + 200;         // 200
    float* c0_s  = q_s + 200;           // 200
    float* G_s   = c0_s + 200;          // 800
    float* wx_s  = G_s + 800;           // 800
    float* W1_s  = wx_s + 800;          // 100*201 (padded stride -> no bank conflict)
    float* W2_s  = W1_s + 100 * 201;    // 50*101
    float* W3_s  = W2_s + 50 * 101;     // 50
    float* b1_s  = W3_s + 50;           // 100
    float* b2_s  = b1_s + 100;          // 50
    float* out_s = b2_s + 50;           // 200
    float* o1_s  = out_s + 200;         // 100
    float* o2_s  = o1_s + 100;          // 50
    float* xv    = o2_s + 50;           // 1

    const int b = blockIdx.x, tid = threadIdx.x;
    for (int i = tid; i < 200; i += 256) {
        ctx_s[i] = g_ctx[b * 200 + i];
        q_s[i]   = h0[b * 200 + i];
        c0_s[i]  = c0[b * 200 + i];
    }
    for (int i = tid; i < 100 * 200; i += 256)
        W1_s[(i / 200) * 201 + (i % 200)] = W1[i];
    for (int i = tid; i < 50 * 100; i += 256)
        W2_s[(i / 100) * 101 + (i % 100)] = W2[i];
    for (int i = tid; i < 50;  i += 256) W3_s[i] = W3[i];
    for (int i = tid; i < 100; i += 256) b1_s[i] = b1[i];
    for (int i = tid; i < 50;  i += 256) b2_s[i] = b2[i];
    for (int i = tid; i < 800; i += 256) wx_s[i] = W_ih[i * 201];
    if (tid == 0) xv[0] = x_in[b];
    __syncthreads();

    // G_const[g] = b_ih + b_hh + ctx@W_ih[:,1:]^T + q@W_hh^T
    for (int gi = tid; gi < 800; gi += 256) {
        float acc = b_ih[gi] + b_hh[gi];
        const float* wi = W_ih + gi * 201 + 1;
        const float* wh = W_hh + gi * 200;
        #pragma unroll 4
        for (int k = 0; k < 200; k++) acc += ctx_s[k] * wi[k];
        #pragma unroll 4
        for (int k = 0; k < 200; k++) acc += q_s[k] * wh[k];
        G_s[gi] = acc;
    }
    const float b3v = b3[0];

    for (int s = 0; s < 5; s++) {
        __syncthreads();
        const float x = xv[0];
        if (tid < 200) {
            float ig = G_s[tid]       + x * wx_s[tid];
            float fg = G_s[200 + tid] + x * wx_s[200 + tid];
            float gg = G_s[400 + tid] + x * wx_s[400 + tid];
            float og = G_s[600 + tid] + x * wx_s[600 + tid];
            float si = 1.f / (1.f + __expf(-ig));
            float sf = 1.f / (1.f + __expf(-fg));
            float so = 1.f / (1.f + __expf(-og));
            float cn = sf * c0_s[tid] + si * tanhf(gg);
            float hn = so * tanhf(cn);
            out_s[tid] = fmaxf(hn, 0.f);
        }
        __syncthreads();
        if (tid < 100) {
            float a = b1_s[tid];
            const float* w = W1_s + tid * 201;
            #pragma unroll 4
            for (int k = 0; k < 200; k++) a += w[k] * out_s[k];
            o1_s[tid] = fmaxf(a, 0.f);
        }
        __syncthreads();
        if (tid < 50) {
            float a = b2_s[tid];
            const float* w = W2_s + tid * 101;
            #pragma unroll 4
            for (int k = 0; k < 100; k++) a += w[k] * o1_s[k];
            o2_s[tid] = fmaxf(a, 0.f);
        }
        __syncthreads();
        if (tid < 32) {
            float a = (tid < 50) ? W3_s[tid] * o2_s[tid] : 0.f;
            if (tid < 18) a += W3_s[tid + 32] * o2_s[tid + 32];
            #pragma unroll
            for (int off = 16; off > 0; off >>= 1)
                a += __shfl_xor_sync(0xffffffffu, a, off);
            if (tid == 0) {
                float y = a + b3v;
                out[b * 5 + s] = y;   // [B,5] row-major
                xv[0] = y;            // decoded output feeds back as next input
            }
        }
    }
}

// ---------------------------------------------------------------------------
extern "C" void kernel_launch(void* const* d_in, const int* in_sizes, int n_in,
                              void* d_out, int out_size) {
    const float* x    = (const float*)d_in[0];
    const float* h0   = (const float*)d_in[1];
    const float* c0   = (const float*)d_in[2];
    const float* enc  = (const float*)d_in[3];
    const float* Wa   = (const float*)d_in[4];
    const float* ba   = (const float*)d_in[5];
    const float* Ua   = (const float*)d_in[6];
    const float* bua  = (const float*)d_in[7];
    const float* Va   = (const float*)d_in[8];
    // d_in[9] = bva: constant added to all scores -> softmax-invariant, skipped
    const float* W_ih = (const float*)d_in[10];
    const float* W_hh = (const float*)d_in[11];
    const float* b_ih = (const float*)d_in[12];
    const float* b_hh = (const float*)d_in[13];
    const float* W1   = (const float*)d_in[14];
    const float* b1   = (const float*)d_in[15];
    const float* W2   = (const float*)d_in[16];
    const float* b2   = (const float*)d_in[17];
    const float* W3   = (const float*)d_in[18];
    const float* b3   = (const float*)d_in[19];
    float* out = (float*)d_out;

    const int smem1 = (HP * HDIM + TILE_T * HDIM + HP + HP +
                       2 * TILE_T + TILE_T + HDIM + 8) * (int)sizeof(float);
    const int smem2 = (200 * 3 + 800 * 2 + 100 * 201 + 50 * 101 + 50 +
                       100 + 50 + 200 + 100 + 50 + 4) * (int)sizeof(float);
    cudaFuncSetAttribute(attn_kernel, cudaFuncAttributeMaxDynamicSharedMemorySize, smem1);
    cudaFuncSetAttribute(dec_kernel,  cudaFuncAttributeMaxDynamicSharedMemorySize, smem2);

    qp_kernel<<<BDIM, 256>>>(h0, Wa, ba, bua);
    attn_kernel<<<BDIM, 256, smem1>>>(enc, Ua, Va);
    dec_kernel<<<BDIM, 256, smem2>>>(x, h0, c0, W_ih, W_hh, b_ih, b_hh,
                                     W1, b1, W2, b2, W3, b3, out);
}

// round 9
// speedup vs baseline: 1.7443x; 1.7443x over previous
#include <cuda_runtime.h>
#include <cstdint>

// Problem constants
#define BDIM 128
#define TDIM 2048
#define HDIM 200
#define HP   208      // padded h extent for mma N-tiling (rows >=200 handled by clamp)
#define TILE_T 64
#define NKSTEP 25     // 200 / 8
#define US   204      // smem row stride: 204 mod 32 = 12 -> (12g+c) is a bank bijection

// Scratch (allocation-free rule: __device__ globals)
__device__ float g_ctxT[HDIM * BDIM];   // context, transposed [h][b]
__device__ float g_h0T[HDIM * BDIM];    // h0, transposed [h][b]
__device__ float g_GT[800 * BDIM];      // LSTM constant gate term, transposed [gi][b]

__device__ __forceinline__ float cvt_tf32(float x) {
    uint32_t u;
    asm("cvt.rna.tf32.f32 %0, %1;" : "=r"(u) : "f"(x));
    return __uint_as_float(u);
}

__device__ __forceinline__ void mma_tf32(float* d,
    uint32_t a0, uint32_t a1, uint32_t a2, uint32_t a3,
    uint32_t b0, uint32_t b1) {
    asm volatile(
        "mma.sync.aligned.m16n8k8.row.col.f32.tf32.tf32.f32 "
        "{%0,%1,%2,%3}, {%4,%5,%6,%7}, {%8,%9}, {%0,%1,%2,%3};"
        : "+f"(d[0]), "+f"(d[1]), "+f"(d[2]), "+f"(d[3])
        : "r"(a0), "r"(a1), "r"(a2), "r"(a3), "r"(b0), "r"(b1));
}

// ---------------------------------------------------------------------------
// Kernel 1: fused qp + scores (tf32 mma) + tanh/Va epilogue + online softmax +
//           context. One CTA per batch, Ua resident in smem (stride 204).
// smem total: (200*204 + 64*204 + 208 + 208 + 128 + 64 + 200 + 200 + 8)*4
//           = 219488 bytes  (< 220864 proven-safe in round 4)
// ---------------------------------------------------------------------------
__global__ void __launch_bounds__(256, 1)
attn_kernel(const float* __restrict__ enc,
            const float* __restrict__ Ua,
            const float* __restrict__ Va,
            const float* __restrict__ h0,
            const float* __restrict__ Wa,
            const float* __restrict__ ba,
            const float* __restrict__ bua) {
    extern __shared__ float sm[];
    float* Ua_s  = sm;                       // HDIM*US (tf32-rounded)
    float* E_s   = Ua_s + HDIM * US;         // TILE_T*US (tf32-rounded)
    float* qp_s  = E_s + TILE_T * US;        // HP (zero for i>=200)
    float* va_s  = qp_s + HP;                // HP (zero for i>=200)
    float* s_s   = va_s + HP;                // 2*TILE_T
    float* w_s   = s_s + 2 * TILE_T;         // TILE_T
    float* ctx_s = w_s + TILE_T;             // HDIM
    float* q_s   = ctx_s + HDIM;             // HDIM (h0 row)
    float* scal  = q_s + HDIM;               // [0]=m, [1]=l, [2]=scale, [3]=newm

    const int b = blockIdx.x, tid = threadIdx.x;

    for (int i = tid; i < HDIM; i += 256) q_s[i] = h0[b * HDIM + i];
    __syncthreads();

    // Ua (tf32-rounded) into stride-204 smem
    const float4* Ua4 = (const float4*)Ua;
    for (int i = tid; i < HDIM * (HDIM / 4); i += 256) {
        int row = i / (HDIM / 4), c4 = i % (HDIM / 4);
        float4 v = Ua4[i];
        v.x = cvt_tf32(v.x); v.y = cvt_tf32(v.y);
        v.z = cvt_tf32(v.z); v.w = cvt_tf32(v.w);
        ((float4*)(Ua_s + row * US))[c4] = v;
    }

    // qp[i] = h0[b]@Wa^T + ba + bua (hides under Ua fill)
    for (int i = tid; i < HP; i += 256) {
        float acc = 0.f;
        if (i < HDIM) {
            acc = ba[i] + bua[i];
            const float* w = Wa + i * HDIM;
            #pragma unroll 8
            for (int k = 0; k < HDIM; k++) acc += q_s[k] * w[k];
        }
        qp_s[i] = acc;
    }
    for (int i = tid; i < HP; i += 256) va_s[i] = (i < HDIM) ? Va[i] : 0.f;
    for (int i = tid; i < HDIM; i += 256) ctx_s[i] = 0.f;
    if (tid == 0) { scal[0] = -1e30f; scal[1] = 0.f; }
    __syncthreads();

    const int lane = tid & 31;
    const int wid  = tid >> 5;
    const int g    = lane >> 2;   // groupID
    const int c    = lane & 3;    // threadID_in_group
    const int wm   = wid & 3;     // t sub-tile (16 rows each)
    const int wn   = wid >> 2;    // h half (104 each)
    const int arow0 = 16 * wm + g;

    for (int tile = 0; tile < TDIM / TILE_T; ++tile) {
        // ---- load E tile into stride-204 smem, tf32-round once ----
        const float4* ep4 =
            (const float4*)(enc + ((size_t)b * TDIM + (size_t)tile * TILE_T) * HDIM);
        for (int i = tid; i < TILE_T * (HDIM / 4); i += 256) {
            int row = i / (HDIM / 4), c4 = i % (HDIM / 4);
            float4 v = ep4[i];
            v.x = cvt_tf32(v.x); v.y = cvt_tf32(v.y);
            v.z = cvt_tf32(v.z); v.w = cvt_tf32(v.w);
            ((float4*)(E_s + row * US))[c4] = v;
        }
        __syncthreads();

        // ---- GEMM: C[t,h] = sum_k E[t,k] * Ua[h,k] ----
        float acc[13][4];
        #pragma unroll
        for (int j = 0; j < 13; j++) {
            acc[j][0] = 0.f; acc[j][1] = 0.f; acc[j][2] = 0.f; acc[j][3] = 0.f;
        }
        const float* Ea = E_s + arow0 * US;
        const float* Eb = Ea + 8 * US;
        #pragma unroll 5
        for (int ks = 0; ks < NKSTEP; ks++) {
            const int kb = ks * 8;
            uint32_t a0 = __float_as_uint(Ea[kb + c]);
            uint32_t a1 = __float_as_uint(Eb[kb + c]);
            uint32_t a2 = __float_as_uint(Ea[kb + c + 4]);
            uint32_t a3 = __float_as_uint(Eb[kb + c + 4]);
            #pragma unroll
            for (int j = 0; j < 13; j++) {
                int hrow = 104 * wn + 8 * j + g;
                // clamp: rows >=200 duplicate row 199 (broadcast load, epilogue
                // multiplies these lanes by va_s==0, so result is exact)
                if (hrow >= HDIM) hrow = HDIM - 1;
                uint32_t b0 = __float_as_uint(Ua_s[hrow * US + kb + c]);
                uint32_t b1 = __float_as_uint(Ua_s[hrow * US + kb + c + 4]);
                mma_tf32(acc[j], a0, a1, a2, a3, b0, b1);
            }
        }

        // ---- epilogue: s[t] partial = sum_h Va[h]*tanh(qp[h]+C[t,h]) ----
        float p0 = 0.f, p8 = 0.f;
        #pragma unroll
        for (int j = 0; j < 13; j++) {
            const int hb = 104 * wn + 8 * j + 2 * c;
            p0 += va_s[hb]     * tanhf(qp_s[hb]     + acc[j][0]);
            p0 += va_s[hb + 1] * tanhf(qp_s[hb + 1] + acc[j][1]);
            p8 += va_s[hb]     * tanhf(qp_s[hb]     + acc[j][2]);
            p8 += va_s[hb + 1] * tanhf(qp_s[hb + 1] + acc[j][3]);
        }
        p0 += __shfl_xor_sync(0xffffffffu, p0, 1);
        p0 += __shfl_xor_sync(0xffffffffu, p0, 2);
        p8 += __shfl_xor_sync(0xffffffffu, p8, 1);
        p8 += __shfl_xor_sync(0xffffffffu, p8, 2);
        if (c == 0) {   // deterministic: each (wn,row) slot written by one lane
            s_s[wn * TILE_T + 16 * wm + g]     = p0;
            s_s[wn * TILE_T + 16 * wm + g + 8] = p8;
        }
        __syncthreads();
        if (tid < TILE_T) s_s[tid] = s_s[tid] + s_s[TILE_T + tid];
        __syncthreads();

        // ---- online softmax update ----
        if (tid < 32) {
            float v = fmaxf(s_s[tid], s_s[tid + 32]);
            #pragma unroll
            for (int off = 16; off > 0; off >>= 1)
                v = fmaxf(v, __shfl_xor_sync(0xffffffffu, v, off));
            if (tid == 0) {
                float mo = scal[0];
                float nm = fmaxf(mo, v);
                scal[2] = __expf(mo - nm);
                scal[3] = nm;
                scal[0] = nm;
            }
        }
        __syncthreads();
        const float nm = scal[3], scale = scal[2];
        if (tid < TILE_T) w_s[tid] = __expf(s_s[tid] - nm);
        __syncthreads();
        if (tid < 32) {
            float sv = w_s[tid] + w_s[tid + 32];
            #pragma unroll
            for (int off = 16; off > 0; off >>= 1)
                sv += __shfl_xor_sync(0xffffffffu, sv, off);
            if (tid == 0) scal[1] = scal[1] * scale + sv;
        }
        // ---- context accumulation from the E tile already in smem ----
        if (tid < HDIM) {
            float a = ctx_s[tid] * scale;
            const float* ec = E_s + tid;
            #pragma unroll 8
            for (int t = 0; t < TILE_T; t++) a += w_s[t] * ec[t * US];
            ctx_s[tid] = a;
        }
        __syncthreads();
    }
    if (tid < HDIM) {
        g_ctxT[tid * BDIM + b] = ctx_s[tid] / scal[1];
        g_h0T[tid * BDIM + b]  = q_s[tid];
    }
}

// ---------------------------------------------------------------------------
// Kernel 2: G_const[b][gi] = b_ih+b_hh + ctx@W_ih[:,1:]^T + h0@W_hh^T
// Warps span b -> weight loads warp-uniform (broadcast), activation loads
// coalesced from transposed copies.
// ---------------------------------------------------------------------------
__global__ void __launch_bounds__(256)
gconst_kernel(const float* __restrict__ W_ih, const float* __restrict__ W_hh,
              const float* __restrict__ b_ih, const float* __restrict__ b_hh) {
    const int idx = blockIdx.x * 256 + threadIdx.x;   // 800*128 threads
    const int b  = idx & (BDIM - 1);
    const int gi = idx >> 7;
    const float* wi = W_ih + gi * 201 + 1;
    const float* wh = W_hh + gi * HDIM;
    const float* ct = g_ctxT + b;
    const float* ht = g_h0T + b;
    float acc = b_ih[gi] + b_hh[gi];
    #pragma unroll 8
    for (int k = 0; k < HDIM; k++)
        acc += ct[k * BDIM] * wi[k] + ht[k * BDIM] * wh[k];
    g_GT[gi * BDIM + b] = acc;
}

// ---------------------------------------------------------------------------
// Kernel 3: per-batch 5-step recurrence entirely in smem.
// ---------------------------------------------------------------------------
__global__ void __launch_bounds__(256, 1)
dec_kernel(const float* __restrict__ x_in, const float* __restrict__ c0,
           const float* __restrict__ W_ih,
           const float* __restrict__ W1, const float* __restrict__ b1,
           const float* __restrict__ W2, const float* __restrict__ b2,
           const float* __restrict__ W3, const float* __restrict__ b3,
           float* __restrict__ out) {
    extern __shared__ float sm[];
    float* c0_s  = sm;                  // 200
    float* G_s   = c0_s + 200;          // 800
    float* wx_s  = G_s + 800;           // 800
    float* W1_s  = wx_s + 800;          // 100*201 (padded stride)
    float* W2_s  = W1_s + 100 * 201;    // 50*101
    float* W3_s  = W2_s + 50 * 101;     // 50
    float* b1_s  = W3_s + 50;           // 100
    float* b2_s  = b1_s + 100;          // 50
    float* out_s = b2_s + 50;           // 200
    float* o1_s  = out_s + 200;         // 100
    float* o2_s  = o1_s + 100;          // 50
    float* xv    = o2_s + 50;           // 1

    const int b = blockIdx.x, tid = threadIdx.x;
    for (int i = tid; i < 200; i += 256) c0_s[i] = c0[b * 200 + i];
    for (int i = tid; i < 800; i += 256) {
        G_s[i]  = g_GT[i * BDIM + b];
        wx_s[i] = W_ih[i * 201];
    }
    for (int i = tid; i < 100 * 200; i += 256)
        W1_s[(i / 200) * 201 + (i % 200)] = W1[i];
    for (int i = tid; i < 50 * 100; i += 256)
        W2_s[(i / 100) * 101 + (i % 100)] = W2[i];
    for (int i = tid; i < 50;  i += 256) W3_s[i] = W3[i];
    for (int i = tid; i < 100; i += 256) b1_s[i] = b1[i];
    for (int i = tid; i < 50;  i += 256) b2_s[i] = b2[i];
    if (tid == 0) xv[0] = x_in[b];
    const float b3v = b3[0];

    for (int s = 0; s < 5; s++) {
        __syncthreads();
        const float x = xv[0];
        if (tid < 200) {
            float ig = G_s[tid]       + x * wx_s[tid];
            float fg = G_s[200 + tid] + x * wx_s[200 + tid];
            float gg = G_s[400 + tid] + x * wx_s[400 + tid];
            float og = G_s[600 + tid] + x * wx_s[600 + tid];
            float si = 1.f / (1.f + __expf(-ig));
            float sf = 1.f / (1.f + __expf(-fg));
            float so = 1.f / (1.f + __expf(-og));
            float cn = sf * c0_s[tid] + si * tanhf(gg);
            float hn = so * tanhf(cn);
            out_s[tid] = fmaxf(hn, 0.f);
        }
        __syncthreads();
        if (tid < 100) {
            float a = b1_s[tid];
            const float* w = W1_s + tid * 201;
            #pragma unroll 8
            for (int k = 0; k < 200; k++) a += w[k] * out_s[k];
            o1_s[tid] = fmaxf(a, 0.f);
        }
        __syncthreads();
        if (tid < 50) {
            float a = b2_s[tid];
            const float* w = W2_s + tid * 101;
            #pragma unroll 4
            for (int k = 0; k < 100; k++) a += w[k] * o1_s[k];
            o2_s[tid] = fmaxf(a, 0.f);
        }
        __syncthreads();
        if (tid < 32) {
            float a = (tid < 50) ? W3_s[tid] * o2_s[tid] : 0.f;
            if (tid < 18) a += W3_s[tid + 32] * o2_s[tid + 32];
            #pragma unroll
            for (int off = 16; off > 0; off >>= 1)
                a += __shfl_xor_sync(0xffffffffu, a, off);
            if (tid == 0) {
                float y = a + b3v;
                out[b * 5 + s] = y;   // [B,5] row-major
                xv[0] = y;            // feeds back as next input
            }
        }
    }
}

// ---------------------------------------------------------------------------
extern "C" void kernel_launch(void* const* d_in, const int* in_sizes, int n_in,
                              void* d_out, int out_size) {
    const float* x    = (const float*)d_in[0];
    const float* h0   = (const float*)d_in[1];
    const float* c0   = (const float*)d_in[2];
    const float* enc  = (const float*)d_in[3];
    const float* Wa   = (const float*)d_in[4];
    const float* ba   = (const float*)d_in[5];
    const float* Ua   = (const float*)d_in[6];
    const float* bua  = (const float*)d_in[7];
    const float* Va   = (const float*)d_in[8];
    // d_in[9] = bva: softmax-invariant constant, skipped
    const float* W_ih = (const float*)d_in[10];
    const float* W_hh = (const float*)d_in[11];
    const float* b_ih = (const float*)d_in[12];
    const float* b_hh = (const float*)d_in[13];
    const float* W1   = (const float*)d_in[14];
    const float* b1   = (const float*)d_in[15];
    const float* W2   = (const float*)d_in[16];
    const float* b2   = (const float*)d_in[17];
    const float* W3   = (const float*)d_in[18];
    const float* b3   = (const float*)d_in[19];
    float* out = (float*)d_out;

    const int smem1 = (HDIM * US + TILE_T * US + HP + HP +
                       2 * TILE_T + TILE_T + HDIM + HDIM + 8) * (int)sizeof(float);
    const int smem2 = (200 + 800 * 2 + 100 * 201 + 50 * 101 + 50 +
                       100 + 50 + 200 + 100 + 50 + 4) * (int)sizeof(float);
    cudaFuncSetAttribute(attn_kernel, cudaFuncAttributeMaxDynamicSharedMemorySize, smem1);
    cudaFuncSetAttribute(dec_kernel,  cudaFuncAttributeMaxDynamicSharedMemorySize, smem2);

    attn_kernel<<<BDIM, 256, smem1>>>(enc, Ua, Va, h0, Wa, ba, bua);
    gconst_kernel<<<(800 * BDIM) / 256, 256>>>(W_ih, W_hh, b_ih, b_hh);
    dec_kernel<<<BDIM, 256, smem2>>>(x, c0, W_ih, W1, b1, W2, b2, W3, b3, out);
}